// round 1
// baseline (speedup 1.0000x reference)
#include <cuda_runtime.h>
#include <cstdint>
#include <cstdio>

#define T_SEQ 512
#define B_TOT 512
#define H_DIM 128
#define G3    384   // 3*H

// ---------------- scratch (no allocations allowed) ----------------
__device__ float g_gi[(size_t)B_TOT * T_SEQ * G3];     // 402 MB, reused for both layers
__device__ float g_h1[(size_t)B_TOT * T_SEQ * H_DIM];  // 134 MB

// ---------------- f32x2 helpers ----------------
__device__ __forceinline__ unsigned long long pack2(float lo, float hi) {
    unsigned long long r;
    asm("mov.b64 %0, {%1, %2};" : "=l"(r) : "f"(lo), "f"(hi));
    return r;
}
__device__ __forceinline__ void unpack2(unsigned long long v, float& lo, float& hi) {
    asm("mov.b64 {%0, %1}, %2;" : "=f"(lo), "=f"(hi) : "l"(v));
}
__device__ __forceinline__ unsigned long long ffma2(unsigned long long a,
                                                    unsigned long long b,
                                                    unsigned long long c) {
    unsigned long long d;
    asm("fma.rn.f32x2 %0, %1, %2, %3;" : "=l"(d) : "l"(a), "l"(b), "l"(c));
    return d;
}

__device__ __forceinline__ float sigf(float x) {
    return 1.0f / (1.0f + __expf(-x));
}

// ---------------------------------------------------------------------------
// Kernel A/C: gi[M,384] = X[M,K] @ W[384,K]^T + bias[384]
// Block: 32 rows x 384 cols, 384 threads. Thread = 1 column x 16 row-pairs.
// f32x2 packing over row pairs; W streamed from L1/L2 (each row read by 1 thread).
// ---------------------------------------------------------------------------
template<int K>
__global__ __launch_bounds__(384, 2)
void gemm_ih(const float* __restrict__ X, const float* __restrict__ W,
             const float* __restrict__ bias, float* __restrict__ out)
{
    extern __shared__ float xs[];  // [K][32], pair-packed by natural row order
    const int tid = threadIdx.x;
    const int r0  = blockIdx.x * 32;

    // stage X tile: element (r,k) -> xs[k*32 + r]
    for (int idx = tid; idx < 32 * K; idx += 384) {
        const int r = idx / K;
        const int k = idx - r * K;
        xs[k * 32 + r] = X[(size_t)(r0 + r) * K + k];
    }
    __syncthreads();

    const int j = tid;
    const float* wr = W + (size_t)j * K;
    const float bj = bias[j];
    unsigned long long acc[16];
    {
        const unsigned long long bp = pack2(bj, bj);
#pragma unroll
        for (int p = 0; p < 16; p++) acc[p] = bp;
    }

    float4 wv = *(const float4*)(wr);
#pragma unroll 1
    for (int kq = 0; kq < K / 4; kq++) {
        const int kn = (kq + 1 < K / 4) ? (kq + 1) : kq;
        const float4 wn = *(const float4*)(wr + 4 * kn);
#pragma unroll
        for (int kk = 0; kk < 4; kk++) {
            float w;
            if (kk == 0) w = wv.x; else if (kk == 1) w = wv.y;
            else if (kk == 2) w = wv.z; else w = wv.w;
            const unsigned long long wd = pack2(w, w);
            const ulonglong2* xq = (const ulonglong2*)(xs + (kq * 4 + kk) * 32);
#pragma unroll
            for (int p = 0; p < 8; p++) {
                const ulonglong2 xv = xq[p];
                acc[2 * p]     = ffma2(wd, xv.x, acc[2 * p]);
                acc[2 * p + 1] = ffma2(wd, xv.y, acc[2 * p + 1]);
            }
        }
        wv = wn;
    }

#pragma unroll
    for (int p = 0; p < 16; p++) {
        float lo, hi;
        unpack2(acc[p], lo, hi);
        out[(size_t)(r0 + 2 * p) * G3 + j]     = lo;
        out[(size_t)(r0 + 2 * p + 1) * G3 + j] = hi;
    }
}

// ---------------------------------------------------------------------------
// Kernel B/D: GRU recurrence, one layer.
// Grid: 128 blocks x 4 batch rows, 384 threads (thread j owns gate column j).
// W_hh in smem, row-major padded to 132 floats/row (conflict-free LDS.128).
// h in smem as [k][4] (batch-pair packed for f32x2). gi double-buffered with
// one-step global prefetch. Layer 2 fuses the final FC.
// ---------------------------------------------------------------------------
#define W_PAD 132
#define SMEM_REC_FLOATS (384 * W_PAD + 512 + 4 * 384 + 2 * 4 * 384)
#define SMEM_REC_BYTES  (SMEM_REC_FLOATS * 4)

template<bool LAYER1>
__global__ __launch_bounds__(384, 1)
void gru_recur(const float* __restrict__ Whh, const float* __restrict__ bhh,
               const float* __restrict__ gi, float* __restrict__ h1out,
               const float* __restrict__ Wfc, const float* __restrict__ bfc,
               float* __restrict__ out)
{
    extern __shared__ float sm[];
    float* w_s  = sm;                         // 384*132
    float* h_s  = w_s + 384 * W_PAD;          // [128][4]  (pairs (b0,b1),(b2,b3))
    float* gh_s = h_s + 512;                  // [4][384]
    float* gi_s = gh_s + 4 * 384;             // [2][4][384]

    const int tid = threadIdx.x;
    const int j   = tid;
    const int b0  = blockIdx.x * 4;

    // load W_hh -> padded smem rows (coalesced global reads)
    for (int idx = tid; idx < 384 * 128; idx += 384) {
        const int jj = idx >> 7;
        const int kk = idx & 127;
        w_s[jj * W_PAD + kk] = Whh[idx];
    }
    for (int i = tid; i < 512; i += 384) h_s[i] = 0.0f;

    // preload gi for t=0 into buffer 0
#pragma unroll
    for (int b = 0; b < 4; b++)
        gi_s[b * 384 + j] = gi[((size_t)(b0 + b) * T_SEQ) * G3 + j];

    const float bh = bhh[j];
    __syncthreads();

    for (int t = 0; t < T_SEQ; t++) {
        float* gin = gi_s + (t & 1) * 1536;
        float* gip = gi_s + ((t + 1) & 1) * 1536;

        // prefetch gi(t+1) from global (consumed ~2k cycles later)
        float gv0 = 0.f, gv1 = 0.f, gv2 = 0.f, gv3 = 0.f;
        const bool pf = (t + 1 < T_SEQ);
        if (pf) {
            const float* gb = gi + ((size_t)b0 * T_SEQ + (t + 1)) * G3 + j;
            gv0 = gb[0];
            gv1 = gb[(size_t)T_SEQ * G3];
            gv2 = gb[(size_t)2 * T_SEQ * G3];
            gv3 = gb[(size_t)3 * T_SEQ * G3];
        }

        // gh[b][j] = b_hh[j] + sum_k h[b][k] * Whh[j][k]   (f32x2 over batch pairs)
        unsigned long long a01 = pack2(bh, bh);
        unsigned long long a23 = a01;
        const float* wj = w_s + j * W_PAD;
#pragma unroll
        for (int k = 0; k < 128; k++) {
            const float w = wj[k];
            const unsigned long long wd = pack2(w, w);
            const ulonglong2 hv = *(const ulonglong2*)(h_s + k * 4);
            a01 = ffma2(wd, hv.x, a01);
            a23 = ffma2(wd, hv.y, a23);
        }
        {
            float g0, g1, g2, g3;
            unpack2(a01, g0, g1);
            unpack2(a23, g2, g3);
            gh_s[j]            = g0;
            gh_s[384 + j]      = g1;
            gh_s[2 * 384 + j]  = g2;
            gh_s[3 * 384 + j]  = g3;
        }
        __syncthreads();

        // gates + state update (512 items over 384 threads)
        for (int i = tid; i < 512; i += 384) {
            const int b  = i >> 7;
            const int jh = i & 127;
            const float* gib = gin + b * 384;
            const float* ghb = gh_s + b * 384;
            const float r = sigf(gib[jh]       + ghb[jh]);
            const float z = sigf(gib[jh + 128] + ghb[jh + 128]);
            const float n = tanhf(gib[jh + 256] + r * ghb[jh + 256]);
            const float ho = h_s[jh * 4 + b];
            const float hn = n + z * (ho - n);
            h_s[jh * 4 + b] = hn;
            if (LAYER1)
                h1out[((size_t)(b0 + b) * T_SEQ + t) * H_DIM + jh] = hn;
        }
        if (pf) {
            gip[j]            = gv0;
            gip[384 + j]      = gv1;
            gip[2 * 384 + j]  = gv2;
            gip[3 * 384 + j]  = gv3;
        }
        __syncthreads();
    }

    if (!LAYER1) {
        // out[b] = h_T[b] . W_fc + b_fc   (4 warps, one batch row each)
        if (tid < 128) {
            const int w = tid >> 5;
            const int l = tid & 31;
            float s = 0.0f;
#pragma unroll
            for (int q = 0; q < 4; q++) {
                const int jh = l + 32 * q;
                s += h_s[jh * 4 + w] * Wfc[jh];
            }
#pragma unroll
            for (int off = 16; off; off >>= 1)
                s += __shfl_down_sync(0xffffffffu, s, off);
            if (l == 0) out[b0 + w] = s + bfc[0];
        }
    }
}

// ---------------------------------------------------------------------------
extern "C" void kernel_launch(void* const* d_in, const int* in_sizes, int n_in,
                              void* d_out, int out_size)
{
    const float* x     = (const float*)d_in[0];
    const float* W_ih0 = (const float*)d_in[1];
    const float* W_hh0 = (const float*)d_in[2];
    const float* b_ih0 = (const float*)d_in[3];
    const float* b_hh0 = (const float*)d_in[4];
    const float* W_ih1 = (const float*)d_in[5];
    const float* W_hh1 = (const float*)d_in[6];
    const float* b_ih1 = (const float*)d_in[7];
    const float* b_hh1 = (const float*)d_in[8];
    const float* W_fc  = (const float*)d_in[9];
    const float* b_fc  = (const float*)d_in[10];
    float* out = (float*)d_out;

    void *gi_p = nullptr, *h1_p = nullptr;
    cudaGetSymbolAddress(&gi_p, g_gi);
    cudaGetSymbolAddress(&h1_p, g_h1);
    float* gi = (float*)gi_p;
    float* h1 = (float*)h1_p;

    cudaFuncSetAttribute(gru_recur<true>,  cudaFuncAttributeMaxDynamicSharedMemorySize, SMEM_REC_BYTES);
    cudaFuncSetAttribute(gru_recur<false>, cudaFuncAttributeMaxDynamicSharedMemorySize, SMEM_REC_BYTES);

    const int M = B_TOT * T_SEQ;  // 262144

    // layer 1: input GEMM + recurrence (writes h1)
    gemm_ih<64><<<M / 32, 384, 64 * 32 * 4>>>(x, W_ih0, b_ih0, gi);
    gru_recur<true><<<128, 384, SMEM_REC_BYTES>>>(W_hh0, b_hh0, gi, h1,
                                                  nullptr, nullptr, nullptr);
    // layer 2: input GEMM (from h1) + recurrence (fused FC)
    gemm_ih<128><<<M / 32, 384, 128 * 32 * 4>>>(h1, W_ih1, b_ih1, gi);
    gru_recur<false><<<128, 384, SMEM_REC_BYTES>>>(W_hh1, b_hh1, gi, nullptr,
                                                   W_fc, b_fc, out);
}

// round 2
// speedup vs baseline: 1.1995x; 1.1995x over previous
#include <cuda_runtime.h>
#include <cstdint>
#include <cstdio>

#define T_SEQ 512
#define B_TOT 512
#define H_DIM 128
#define G3    384   // 3*H

// ---------------- scratch (no allocations allowed) ----------------
__device__ float g_gi[(size_t)B_TOT * T_SEQ * G3];     // 402 MB, reused for both layers
__device__ float g_h1[(size_t)B_TOT * T_SEQ * H_DIM];  // 134 MB

// ---------------- f32x2 helpers ----------------
__device__ __forceinline__ unsigned long long pack2(float lo, float hi) {
    unsigned long long r;
    asm("mov.b64 %0, {%1, %2};" : "=l"(r) : "f"(lo), "f"(hi));
    return r;
}
__device__ __forceinline__ void unpack2(unsigned long long v, float& lo, float& hi) {
    asm("mov.b64 {%0, %1}, %2;" : "=f"(lo), "=f"(hi) : "l"(v));
}
__device__ __forceinline__ unsigned long long ffma2(unsigned long long a,
                                                    unsigned long long b,
                                                    unsigned long long c) {
    unsigned long long d;
    asm("fma.rn.f32x2 %0, %1, %2, %3;" : "=l"(d) : "l"(a), "l"(b), "l"(c));
    return d;
}

__device__ __forceinline__ float sigf(float x) {
    return __fdividef(1.0f, 1.0f + __expf(-x));
}
__device__ __forceinline__ float tanhfast(float x) {
    const float e = __expf(-2.0f * x);
    return __fdividef(1.0f - e, 1.0f + e);
}

// ---------------------------------------------------------------------------
// Kernel A/C: gi[M,384] = X[M,K] @ W[384,K]^T + bias[384]
// Block: 32 rows x 384 cols, 384 threads. Thread = 1 column x 16 row-pairs.
// ---------------------------------------------------------------------------
template<int K>
__global__ __launch_bounds__(384, 2)
void gemm_ih(const float* __restrict__ X, const float* __restrict__ W,
             const float* __restrict__ bias, float* __restrict__ out)
{
    extern __shared__ float xs[];  // [K][32]
    const int tid = threadIdx.x;
    const int r0  = blockIdx.x * 32;

    for (int idx = tid; idx < 32 * K; idx += 384) {
        const int r = idx / K;
        const int k = idx - r * K;
        xs[k * 32 + r] = X[(size_t)(r0 + r) * K + k];
    }
    __syncthreads();

    const int j = tid;
    const float* wr = W + (size_t)j * K;
    const float bj = bias[j];
    unsigned long long acc[16];
    {
        const unsigned long long bp = pack2(bj, bj);
#pragma unroll
        for (int p = 0; p < 16; p++) acc[p] = bp;
    }

    float4 wv = *(const float4*)(wr);
#pragma unroll 1
    for (int kq = 0; kq < K / 4; kq++) {
        const int kn = (kq + 1 < K / 4) ? (kq + 1) : kq;
        const float4 wn = *(const float4*)(wr + 4 * kn);
#pragma unroll
        for (int kk = 0; kk < 4; kk++) {
            float w;
            if (kk == 0) w = wv.x; else if (kk == 1) w = wv.y;
            else if (kk == 2) w = wv.z; else w = wv.w;
            const unsigned long long wd = pack2(w, w);
            const ulonglong2* xq = (const ulonglong2*)(xs + (kq * 4 + kk) * 32);
#pragma unroll
            for (int p = 0; p < 8; p++) {
                const ulonglong2 xv = xq[p];
                acc[2 * p]     = ffma2(wd, xv.x, acc[2 * p]);
                acc[2 * p + 1] = ffma2(wd, xv.y, acc[2 * p + 1]);
            }
        }
        wv = wn;
    }

#pragma unroll
    for (int p = 0; p < 16; p++) {
        float lo, hi;
        unpack2(acc[p], lo, hi);
        out[(size_t)(r0 + 2 * p) * G3 + j]     = lo;
        out[(size_t)(r0 + 2 * p + 1) * G3 + j] = hi;
    }
}

// ---------------------------------------------------------------------------
// Kernel B/D: GRU recurrence, one layer. W_hh lives in REGISTERS (128/thread).
// Grid: 128 blocks x 4 batch rows, 384 threads (thread j owns gate column j).
//
// f32x2 packs K-PAIRS: wd = (W[j][2k], W[j][2k+1]) comes straight from the
// register file (no dup MOV); h is stored in smem as per-batch k-pairs so one
// broadcast LDS.128 feeds two batches. Inner body per k-pair:
//   2x LDS.128(broadcast) + 4x FFMA2  -> FFMA-pipe bound, 25% issue slack.
//
// h_s layout: float2 pair (h[2k],h[2k+1]) for batch b at float offset
//   (k2*4 + b)*2  ==  k2*8 + 2b (+0/1 for even/odd k)
// ---------------------------------------------------------------------------
template<bool LAYER1>
__global__ __launch_bounds__(384, 1)
void gru_recur(const float* __restrict__ Whh, const float* __restrict__ bhh,
               const float* __restrict__ gi, float* __restrict__ h1out,
               const float* __restrict__ Wfc, const float* __restrict__ bfc,
               float* __restrict__ out)
{
    __shared__ float h_s[64 * 8];        // [k2][b][2]  (k-pairs x 4 batches)
    __shared__ float gh_s[4 * 384];      // [b][j]
    __shared__ float gi_s[2 * 4 * 384];  // double-buffered [buf][b][j]

    const int tid = threadIdx.x;
    const int j   = tid;
    const int b0  = blockIdx.x * 4;

    // W row j -> registers, already packed as 64 k-pair doubles
    unsigned long long w2[64];
    {
        const ulonglong2* wp = (const ulonglong2*)(Whh + (size_t)j * H_DIM);
#pragma unroll
        for (int q = 0; q < 32; q++) {
            const ulonglong2 v = wp[q];
            w2[2 * q]     = v.x;
            w2[2 * q + 1] = v.y;
        }
    }
    const float bh = bhh[j];

    for (int i = tid; i < 512; i += 384) h_s[i] = 0.0f;
#pragma unroll
    for (int b = 0; b < 4; b++)
        gi_s[b * 384 + j] = gi[((size_t)(b0 + b) * T_SEQ) * G3 + j];
    __syncthreads();

    for (int t = 0; t < T_SEQ; t++) {
        float* gin = gi_s + (t & 1) * 1536;
        float* gip = gi_s + ((t + 1) & 1) * 1536;

        // prefetch gi(t+1) from global (consumed after the MMA)
        float gv0 = 0.f, gv1 = 0.f, gv2 = 0.f, gv3 = 0.f;
        const bool pf = (t + 1 < T_SEQ);
        if (pf) {
            const float* gb = gi + ((size_t)b0 * T_SEQ + (t + 1)) * G3 + j;
            gv0 = gb[0];
            gv1 = gb[(size_t)T_SEQ * G3];
            gv2 = gb[(size_t)2 * T_SEQ * G3];
            gv3 = gb[(size_t)3 * T_SEQ * G3];
        }

        // gh[b][j] = b_hh[j] + sum_k W[j][k] * h[b][k]
        // acc_b holds (even-k partial, odd-k partial); horizontal add at the end.
        unsigned long long a0 = 0ull, a1 = 0ull, a2 = 0ull, a3 = 0ull;
#pragma unroll
        for (int k2 = 0; k2 < 64; k2++) {
            const ulonglong2 h01 = *(const ulonglong2*)(h_s + k2 * 8);      // b0,b1
            const ulonglong2 h23 = *(const ulonglong2*)(h_s + k2 * 8 + 4);  // b2,b3
            const unsigned long long wd = w2[k2];
            a0 = ffma2(wd, h01.x, a0);
            a1 = ffma2(wd, h01.y, a1);
            a2 = ffma2(wd, h23.x, a2);
            a3 = ffma2(wd, h23.y, a3);
        }
        {
            float lo, hi;
            unpack2(a0, lo, hi); gh_s[j]           = bh + lo + hi;
            unpack2(a1, lo, hi); gh_s[384 + j]     = bh + lo + hi;
            unpack2(a2, lo, hi); gh_s[2 * 384 + j] = bh + lo + hi;
            unpack2(a3, lo, hi); gh_s[3 * 384 + j] = bh + lo + hi;
        }
        __syncthreads();

        // gates + state update (512 items over 384 threads)
        for (int i = tid; i < 512; i += 384) {
            const int b  = i >> 7;
            const int jh = i & 127;
            const float* gib = gin + b * 384;
            const float* ghb = gh_s + b * 384;
            const float r = sigf(gib[jh]       + ghb[jh]);
            const float z = sigf(gib[jh + 128] + ghb[jh + 128]);
            const float n = tanhfast(gib[jh + 256] + r * ghb[jh + 256]);
            const float ho = h_s[(jh >> 1) * 8 + 2 * b + (jh & 1)];
            const float hn = n + z * (ho - n);
            h_s[(jh >> 1) * 8 + 2 * b + (jh & 1)] = hn;
            if (LAYER1)
                h1out[((size_t)(b0 + b) * T_SEQ + t) * H_DIM + jh] = hn;
        }
        if (pf) {
            gip[j]           = gv0;
            gip[384 + j]     = gv1;
            gip[2 * 384 + j] = gv2;
            gip[3 * 384 + j] = gv3;
        }
        __syncthreads();
    }

    if (!LAYER1) {
        // out[b] = h_T[b] . W_fc + b_fc   (4 warps, one batch row each)
        if (tid < 128) {
            const int w = tid >> 5;
            const int l = tid & 31;
            float s = 0.0f;
#pragma unroll
            for (int q = 0; q < 4; q++) {
                const int jh = l + 32 * q;
                s += h_s[(jh >> 1) * 8 + 2 * w + (jh & 1)] * Wfc[jh];
            }
#pragma unroll
            for (int off = 16; off; off >>= 1)
                s += __shfl_down_sync(0xffffffffu, s, off);
            if (l == 0) out[b0 + w] = s + bfc[0];
        }
    }
}

// ---------------------------------------------------------------------------
extern "C" void kernel_launch(void* const* d_in, const int* in_sizes, int n_in,
                              void* d_out, int out_size)
{
    const float* x     = (const float*)d_in[0];
    const float* W_ih0 = (const float*)d_in[1];
    const float* W_hh0 = (const float*)d_in[2];
    const float* b_ih0 = (const float*)d_in[3];
    const float* b_hh0 = (const float*)d_in[4];
    const float* W_ih1 = (const float*)d_in[5];
    const float* W_hh1 = (const float*)d_in[6];
    const float* b_ih1 = (const float*)d_in[7];
    const float* b_hh1 = (const float*)d_in[8];
    const float* W_fc  = (const float*)d_in[9];
    const float* b_fc  = (const float*)d_in[10];
    float* out = (float*)d_out;

    void *gi_p = nullptr, *h1_p = nullptr;
    cudaGetSymbolAddress(&gi_p, g_gi);
    cudaGetSymbolAddress(&h1_p, g_h1);
    float* gi = (float*)gi_p;
    float* h1 = (float*)h1_p;

    const int M = B_TOT * T_SEQ;  // 262144

    // layer 1: input GEMM + recurrence (writes h1)
    gemm_ih<64><<<M / 32, 384, 64 * 32 * 4>>>(x, W_ih0, b_ih0, gi);
    gru_recur<true><<<128, 384>>>(W_hh0, b_hh0, gi, h1,
                                  nullptr, nullptr, nullptr);
    // layer 2: input GEMM (from h1) + recurrence (fused FC)
    gemm_ih<128><<<M / 32, 384, 128 * 32 * 4>>>(h1, W_ih1, b_ih1, gi);
    gru_recur<false><<<128, 384>>>(W_hh1, b_hh1, gi, nullptr,
                                   W_fc, b_fc, out);
}